// round 2
// baseline (speedup 1.0000x reference)
#include <cuda_runtime.h>
#include <math_constants.h>

// ROI max pooling.
// feature_map: (4,4,16,16,512) fp32, rois: (4,4,64,4) fp32
// out: (4,4,64,7,7,512) fp32
//
// Grid: x = global ROI index (B*N*R = 1024), y = bin index (49).
// Block: 128 threads, one float4 channel-group each (C=512 -> 128 groups).

#define FM_H 16
#define FM_W 16
#define FM_C 512
#define PH 7
#define PW 7
#define NROIS_PER_IMG 64
#define C4 (FM_C / 4)   // 128

__global__ __launch_bounds__(C4) void roipool_kernel(
    const float4* __restrict__ fm,    // (16, 16, 16, 512/4)
    const float*  __restrict__ rois,  // (1024, 4)
    float4*       __restrict__ out)   // (1024, 49, 512/4)
{
    const int g   = blockIdx.x;        // image*64 + roi
    const int bin = blockIdx.y;        // 0..48
    const int bi  = bin / PW;
    const int bj  = bin % PW;
    const int img = g / NROIS_PER_IMG;

    const float r0 = __ldg(&rois[g * 4 + 0]);
    const float r1 = __ldg(&rois[g * 4 + 1]);
    const float r2 = __ldg(&rois[g * 4 + 2]);
    const float r3 = __ldg(&rois[g * 4 + 3]);

    // Truncation matches jnp .astype(int32) for positive values.
    const int h0 = (int)((float)FM_H * r0);
    const int w0 = (int)((float)FM_W * r1);
    const int h1 = (int)((float)FM_H * r2);
    const int w1 = (int)((float)FM_W * r3);

    const int hs = (h1 - h0) / PH;   // >= 0 (region positive by construction)
    const int ws = (w1 - w0) / PW;

    // Bin row window [rs, re): bins 0..PH-2 span hs rows; last bin extends to h1.
    // If hs <= 0, ALL in-ROI pixels fold into the last bin (reference semantics);
    // other bins stay -inf.
    int rs, re;
    if (hs > 0) {
        rs = h0 + bi * hs;
        re = (bi == PH - 1) ? h1 : rs + hs;
    } else {
        rs = (bi == PH - 1) ? h0 : 0;
        re = (bi == PH - 1) ? h1 : 0;
    }
    int cs, ce;
    if (ws > 0) {
        cs = w0 + bj * ws;
        ce = (bj == PW - 1) ? w1 : cs + ws;
    } else {
        cs = (bj == PW - 1) ? w0 : 0;
        ce = (bj == PW - 1) ? w1 : 0;
    }

    const int c4 = threadIdx.x;  // 0..127
    const float4* base = fm + (size_t)img * (FM_H * FM_W * C4) + c4;

    float4 m = make_float4(-CUDART_INF_F, -CUDART_INF_F,
                           -CUDART_INF_F, -CUDART_INF_F);

    for (int h = rs; h < re; ++h) {
        const float4* row = base + (size_t)(h * FM_W) * C4;
        for (int w = cs; w < ce; ++w) {
            float4 v = __ldg(row + (size_t)w * C4);
            m.x = fmaxf(m.x, v.x);
            m.y = fmaxf(m.y, v.y);
            m.z = fmaxf(m.z, v.z);
            m.w = fmaxf(m.w, v.w);
        }
    }

    out[((size_t)g * (PH * PW) + bin) * C4 + c4] = m;
}

extern "C" void kernel_launch(void* const* d_in, const int* in_sizes, int n_in,
                              void* d_out, int out_size) {
    const float4* fm   = (const float4*)d_in[0];
    const float*  rois = (const float*)d_in[1];
    float4*       out  = (float4*)d_out;

    const int n_rois_total = in_sizes[1] / 4;  // 1024

    dim3 grid(n_rois_total, PH * PW);
    roipool_kernel<<<grid, C4>>>(fm, rois, out);
}

// round 3
// speedup vs baseline: 1.0397x; 1.0397x over previous
#include <cuda_runtime.h>
#include <math_constants.h>

// ROI max pooling — one block per ROI.
// feature_map: (4,4,16,16,512) fp32 -> viewed (16 images, 16, 16, 128 float4)
// rois: (1024, 4) fp32
// out: (1024, 7, 7, 128 float4)

#define FM_H 16
#define FM_W 16
#define PH 7
#define PW 7
#define C4 128          // 512 channels / 4
#define NROIS_PER_IMG 64

__global__ __launch_bounds__(C4) void roipool_kernel(
    const float4* __restrict__ fm,
    const float4* __restrict__ rois,   // one float4 per ROI
    float4*       __restrict__ out)
{
    const int g   = blockIdx.x;          // global ROI index
    const int img = g / NROIS_PER_IMG;
    const int c4  = threadIdx.x;         // 0..127

    const float4 r = __ldg(&rois[g]);
    // Truncation matches jnp .astype(int32) for positive values.
    const int h0 = (int)((float)FM_H * r.x);
    const int w0 = (int)((float)FM_W * r.y);
    const int h1 = (int)((float)FM_H * r.z);
    const int w1 = (int)((float)FM_W * r.w);
    const int hs = (h1 - h0) / PH;
    const int ws = (w1 - w0) / PW;

    // Column windows per bin-col, reference semantics:
    // bins 0..PW-2 span ws cols; last bin extends to w1. If ws<=0 all in-ROI
    // cols fold into last bin; other bins stay empty (-inf).
    int cs[PW], ce[PW];
    #pragma unroll
    for (int bj = 0; bj < PW; ++bj) {
        if (ws > 0) {
            cs[bj] = w0 + bj * ws;
            ce[bj] = (bj == PW - 1) ? w1 : cs[bj] + ws;
        } else {
            cs[bj] = (bj == PW - 1) ? w0 : 0;
            ce[bj] = (bj == PW - 1) ? w1 : 0;
        }
    }

    const float4* base  = fm + (size_t)img * (FM_H * FM_W * C4) + c4;
    float4*       obase = out + (size_t)g * (PH * PW * C4) + c4;

    for (int bi = 0; bi < PH; ++bi) {
        int rs, re;
        if (hs > 0) {
            rs = h0 + bi * hs;
            re = (bi == PH - 1) ? h1 : rs + hs;
        } else {
            rs = (bi == PH - 1) ? h0 : 0;
            re = (bi == PH - 1) ? h1 : 0;
        }

        float4 acc[PW];
        #pragma unroll
        for (int bj = 0; bj < PW; ++bj)
            acc[bj] = make_float4(-CUDART_INF_F, -CUDART_INF_F,
                                  -CUDART_INF_F, -CUDART_INF_F);

        for (int h = rs; h < re; ++h) {
            const float4* row = base + (size_t)(h * FM_W) * C4;
            #pragma unroll
            for (int bj = 0; bj < PW; ++bj) {
                for (int w = cs[bj]; w < ce[bj]; ++w) {
                    float4 v = __ldg(row + (size_t)w * C4);
                    acc[bj].x = fmaxf(acc[bj].x, v.x);
                    acc[bj].y = fmaxf(acc[bj].y, v.y);
                    acc[bj].z = fmaxf(acc[bj].z, v.z);
                    acc[bj].w = fmaxf(acc[bj].w, v.w);
                }
            }
        }

        #pragma unroll
        for (int bj = 0; bj < PW; ++bj)
            obase[(size_t)(bi * PW + bj) * C4] = acc[bj];
    }
}

extern "C" void kernel_launch(void* const* d_in, const int* in_sizes, int n_in,
                              void* d_out, int out_size) {
    const float4* fm   = (const float4*)d_in[0];
    const float4* rois = (const float4*)d_in[1];
    float4*       out  = (float4*)d_out;

    const int n_rois_total = in_sizes[1] / 4;  // 1024

    roipool_kernel<<<n_rois_total, C4>>>(fm, rois, out);
}